// round 15
// baseline (speedup 1.0000x reference)
#include <cuda_runtime.h>

// RoiPooling: fmap [1,128,128,256] f32 NHWC, roi_edges [R,4] f32
// out [R,7,7,256] f32. Adaptive max pool, reference _bin_size semantics.
//
// Pass 1 build_ty1: Ty1[y] = max(fmap[y], fmap[y+1]) (16.8MB table,
// shared by all ROIs). Pass 2 gather: each cnt-row bin covered by
// ceil(cnt/2) overlapping 2-row windows from Ty1 (cnt==1 -> fmap row).
// Row reads 0.596x => gather reads 116MB. Gather does 2 out-rows per
// block (grid (R,4)) to restore R10's ~28-loads/block granularity and
// halve prologue count. Total L2 traffic ~180MB; LTS-capped => ~15.5us.

#define W_DIM 128
#define C_VEC 64                     // 256 channels / 4 (float4)
#define OUT_H 7
#define OUT_W 7
#define ROWF4 (W_DIM * C_VEC)        // float4 elems per row (8192)

__device__ float4 g_ty1[128][ROWF4]; // row y = max(f[y], f[y+1]), y in [0,127)

__device__ __forceinline__ int bin_size(int L) {
    int xup = (L + OUT_H - 1) / OUT_H;            // ceil(L/7)
    int m = (xup * (OUT_H - 1) >= L) ? (xup - 1) : xup;
    return m > 1 ? m : 1;
}

__device__ __forceinline__ void fold(float4& a, const float4 v) {
    a.x = fmaxf(a.x, v.x);
    a.y = fmaxf(a.y, v.y);
    a.z = fmaxf(a.z, v.z);
    a.w = fmaxf(a.w, v.w);
}

// ---------------- build kernel ----------------
// 4 output rows per thread: 5 independent front-batched loads, 4 stores.
// grid (32, 32) = 1024 blocks -> full-chip parallelism.
__global__ __launch_bounds__(256)
void build_ty1(const float4* __restrict__ fmap)
{
    const int col = blockIdx.x * 256 + threadIdx.x;   // 0..8191
    const int ys  = blockIdx.y * 4;                   // 0,4,...,124

    float4 r[5];
#pragma unroll
    for (int k = 0; k < 5; ++k) {
        int y = ys + k;
        if (y < 128) r[k] = __ldg(fmap + y * ROWF4 + col);
    }
#pragma unroll
    for (int k = 0; k < 4; ++k) {
        int y = ys + k;
        if (y < 127) {
            float4 m;
            m.x = fmaxf(r[k].x, r[k + 1].x);
            m.y = fmaxf(r[k].y, r[k + 1].y);
            m.z = fmaxf(r[k].z, r[k + 1].z);
            m.w = fmaxf(r[k].w, r[k + 1].w);
            g_ty1[y][col] = m;
        }
    }
}

// ---------------- gather kernel ----------------
// One half-block, one out-row. ty=0: bins [0,JS); ty=1: bins [JS,7) incl.
// predicated tail. base = row (t+y0), col l, channel tid in fmap (nr rows
// are single fmap row when cnt==1) or g_ty1 (2-row windows). Window k:
// offset 2k, last window at lastoff (overlap ok, max idempotent).
template<int MW, bool FIRST>
__device__ __forceinline__ void run_row(const float4* __restrict__ base,
                                        int nr, int lastoff, int wl,
                                        float4* __restrict__ obase)
{
    constexpr int JS = (14 * MW + 7) / (4 * MW);   // MW=1..5 -> 5,4,4,3,3
    constexpr int J0 = FIRST ? 0 : JS;
    constexpr int J1 = FIRST ? JS : (OUT_W - 1);   // full-width bins only
    constexpr int NB = (FIRST ? JS : OUT_W - JS);  // accs incl. tail bin
    constexpr int NL = (J1 - J0) * MW;             // batched loads per row

    const float NEG = __int_as_float(0xff800000);   // -inf
    float4 acc[NB];
#pragma unroll
    for (int j = 0; j < NB; ++j)
        acc[j] = make_float4(NEG, NEG, NEG, NEG);

#pragma unroll
    for (int k = 0; k < 3; ++k) {
        if (k >= nr) break;
        const int yoff = (k == nr - 1) ? lastoff : 2 * k;
        const float4* row = base + yoff * ROWF4;

        float4 v[NL];
#pragma unroll
        for (int u = 0; u < NL; ++u)
            v[u] = __ldg(row + (J0 * MW + u) * C_VEC);
#pragma unroll
        for (int u = 0; u < NL; ++u)
            fold(acc[u / MW], v[u]);

        if (!FIRST) {
            const float4* rowt = row + (OUT_W - 1) * MW * C_VEC;
#pragma unroll
            for (int kk = 0; kk < 6; ++kk) {
                if (kk < wl)
                    fold(acc[NB - 1], __ldg(rowt + kk * C_VEC));
            }
        }
    }

#pragma unroll
    for (int j = 0; j < NB; ++j)
        obase[(J0 + j) * C_VEC] = acc[j];
}

// Compute per-out-row window parameters and run. i = out row.
template<int MW, bool FIRST>
__device__ __forceinline__ void do_row(const float4* __restrict__ fmap,
                                       int i, int mh, int Lh,
                                       int rowcol_off, int wl,
                                       float4* __restrict__ oroi)
{
    const int y0 = i * mh;
    int y1 = (i == OUT_H - 1) ? Lh : (i + 1) * mh;
    if (y1 > Lh) y1 = Lh;
    const int cnt = y1 - y0;                       // 1..6

    const int nr      = (cnt + 1) >> 1;            // 1..3 reads
    const int lastoff = (cnt == 1) ? 0 : (cnt - 2);
    const int off     = y0 * ROWF4 + rowcol_off;
    const float4* base = (cnt == 1) ? (fmap + off) : (&g_ty1[0][0] + off);

    run_row<MW, FIRST>(base, nr, lastoff, wl, oroi + i * OUT_W * C_VEC);
}

template<int MW, bool FIRST>
__device__ __forceinline__ void run_pair(const float4* __restrict__ fmap,
                                         int p, int mh, int Lh,
                                         int rowcol_off, int wl,
                                         float4* __restrict__ oroi)
{
    do_row<MW, FIRST>(fmap, p, mh, Lh, rowcol_off, wl, oroi);
    if (p < 3)
        do_row<MW, FIRST>(fmap, p + 4, mh, Lh, rowcol_off, wl, oroi);
}

__global__ __launch_bounds__(128, 6)
void roi_pool_kernel(const float4* __restrict__ fmap,   // [128,128,64] float4
                     const float4* __restrict__ rois,   // [R] (l,r,t,b)
                     float4* __restrict__ out)          // [R,7,7,64] float4
{
    const int r   = blockIdx.x;       // ROI index
    const int p   = blockIdx.y;       // row-pair 0..3 ({p,p+4}; p=3 -> {3})
    const int tid = threadIdx.x;      // 0..63 channel-group
    const bool first = (threadIdx.y == 0);

    const float4 e = rois[r];
    const int l  = __float2int_rn(128.0f * e.x);
    const int rr = __float2int_rn(128.0f * e.y);
    const int t  = __float2int_rn(128.0f * e.z);
    const int b  = __float2int_rn(128.0f * e.w);

    int Lh = b - t; Lh = Lh < OUT_H ? OUT_H : (Lh > 32 ? 32 : Lh);
    int Lw = rr - l; Lw = Lw < OUT_W ? OUT_W : (Lw > 32 ? 32 : Lw);

    const int mh = bin_size(Lh);
    const int mw = bin_size(Lw);
    const int wl = Lw - (OUT_W - 1) * mw;          // last-bin width, 1..6

    // offset of (row t, col l, channel tid); add y0*ROWF4 per out-row.
    const int rowcol_off = (t * W_DIM + l) * C_VEC + tid;
    float4* oroi = out + (r * OUT_H * OUT_W) * C_VEC + tid;

    switch (mw) {
        case 1:
            if (first) run_pair<1, true >(fmap, p, mh, Lh, rowcol_off, wl, oroi);
            else       run_pair<1, false>(fmap, p, mh, Lh, rowcol_off, wl, oroi);
            break;
        case 2:
            if (first) run_pair<2, true >(fmap, p, mh, Lh, rowcol_off, wl, oroi);
            else       run_pair<2, false>(fmap, p, mh, Lh, rowcol_off, wl, oroi);
            break;
        case 3:
            if (first) run_pair<3, true >(fmap, p, mh, Lh, rowcol_off, wl, oroi);
            else       run_pair<3, false>(fmap, p, mh, Lh, rowcol_off, wl, oroi);
            break;
        case 4:
            if (first) run_pair<4, true >(fmap, p, mh, Lh, rowcol_off, wl, oroi);
            else       run_pair<4, false>(fmap, p, mh, Lh, rowcol_off, wl, oroi);
            break;
        default:
            if (first) run_pair<5, true >(fmap, p, mh, Lh, rowcol_off, wl, oroi);
            else       run_pair<5, false>(fmap, p, mh, Lh, rowcol_off, wl, oroi);
            break;
    }
}

extern "C" void kernel_launch(void* const* d_in, const int* in_sizes, int n_in,
                              void* d_out, int out_size)
{
    const float4* fmap = (const float4*)d_in[0];   // [1,128,128,256] f32
    const float4* rois = (const float4*)d_in[1];   // [R,4] f32
    float4* out = (float4*)d_out;

    const int R = in_sizes[1] / 4;

    // Pass 1: build Ty1.
    dim3 bgrid(ROWF4 / 256, 32);
    build_ty1<<<bgrid, 256>>>(fmap);

    // Pass 2: gather, 2 out-rows per block.
    dim3 grid(R, 4);
    dim3 block(C_VEC, 2);
    roi_pool_kernel<<<grid, block>>>(fmap, rois, out);
}